// round 1
// baseline (speedup 1.0000x reference)
#include <cuda_runtime.h>
#include <math.h>

#define Bq 8
#define Cq 256
#define Hq 128
#define Wq 128
#define Pq (Hq*Wq)
#define NHq 8
#define HDq 32
#define NGq (Bq*NHq)

// Scratch (no allocations allowed)
__device__ float g_ix[Bq*NHq*Pq];
__device__ float g_iy[Bq*NHq*Pq];
__device__ float g_V [Bq*Cq*Pq];   // V projection, (B,C,P)
__device__ float g_S [Bq*Cq*Pq];   // bilinear-sampled, (B,C,P)
__device__ float g_sum[NGq];
__device__ float g_sq [NGq];
__device__ float g_mean[NGq];
__device__ float g_rstd[NGq];

__global__ void k_zero() {
    int i = threadIdx.x;
    if (i < NGq) { g_sum[i] = 0.f; g_sq[i] = 0.f; }
}

// Fused: depthwise 3x3 conv -> offset projection (16 ch) -> tanh*0.5 -> grid coords
__global__ void k_offsets(const float* __restrict__ x,
                          const float* __restrict__ dw,
                          const float* __restrict__ offw,
                          const float* __restrict__ offb) {
    int p = blockIdx.x * blockDim.x + threadIdx.x;   // pixel within batch
    int b = blockIdx.y;
    int y = p / Wq, xx = p % Wq;

    float acc[2*NHq];
#pragma unroll
    for (int o = 0; o < 2*NHq; o++) acc[o] = __ldg(offb + o);

    const float* xb = x + (size_t)b * Cq * Pq;
    for (int c = 0; c < Cq; c++) {
        const float* xc = xb + c * Pq;
        float wreg[9];
#pragma unroll
        for (int t = 0; t < 9; t++) wreg[t] = __ldg(dw + c*9 + t);
        float hv = 0.f;
#pragma unroll
        for (int ky = 0; ky < 3; ky++) {
            int yy = y + ky - 1;
            if (yy < 0 || yy >= Hq) continue;
#pragma unroll
            for (int kx = 0; kx < 3; kx++) {
                int xk = xx + kx - 1;
                if (xk < 0 || xk >= Wq) continue;
                hv = fmaf(__ldg(xc + yy*Wq + xk), wreg[ky*3+kx], hv);
            }
        }
#pragma unroll
        for (int o = 0; o < 2*NHq; o++)
            acc[o] = fmaf(hv, __ldg(offw + o*Cq + c), acc[o]);
    }

    float gy = -1.f + 2.f * (float)y  / (float)(Hq - 1);
    float gx = -1.f + 2.f * (float)xx / (float)(Wq - 1);
#pragma unroll
    for (int hh = 0; hh < NHq; hh++) {
        float dy = tanhf(acc[2*hh  ]) * 0.5f;
        float dx = tanhf(acc[2*hh+1]) * 0.5f;
        float sy = fminf(fmaxf(gy + dy, -1.f), 1.f);
        float sx = fminf(fmaxf(gx + dx, -1.f), 1.f);
        g_iy[(b*NHq + hh)*Pq + p] = (sy + 1.f) * 0.5f * (float)(Hq - 1);
        g_ix[(b*NHq + hh)*Pq + p] = (sx + 1.f) * 0.5f * (float)(Wq - 1);
    }
}

// SGEMM: Out[b][o][p] = sum_c A[o][c] * In[b][c][p]
// 64x64x16 tiles, 256 threads, 4x4 micro-tile.
// STATS: fuse per-(b, o/32) sum/sumsq reduction for groupnorm.
template <bool STATS>
__global__ void k_gemm(const float* __restrict__ A,
                       const float* __restrict__ In,
                       float* __restrict__ Out) {
    const int BM = 64, BN = 64, BK = 16;
    __shared__ float As[BK][BM + 1];
    __shared__ float Bs[BK][BN];

    int b  = blockIdx.z;
    int om = blockIdx.y * BM;
    int pn = blockIdx.x * BN;
    int tid = threadIdx.x;
    int tr = tid >> 4;        // 0..15 (row group of 4)
    int tc = tid & 15;        // 0..15 (col group of 4)

    float acc[4][4] = {};
    const float* Bb = In + (size_t)b * Cq * Pq;

    for (int k0 = 0; k0 < Cq; k0 += BK) {
        {   // load A tile 64x16, transposed into As[k][m]
            int row = tid >> 2;
            int cg  = (tid & 3) * 4;
            float4 v = *(const float4*)(A + (size_t)(om + row) * Cq + k0 + cg);
            As[cg+0][row] = v.x; As[cg+1][row] = v.y;
            As[cg+2][row] = v.z; As[cg+3][row] = v.w;
        }
        {   // load B tile 16x64
            int row = tid >> 4;
            int cg  = (tid & 15) * 4;
            float4 v = *(const float4*)(Bb + (size_t)(k0 + row) * Pq + pn + cg);
            *(float4*)&Bs[row][cg] = v;
        }
        __syncthreads();
#pragma unroll
        for (int kk = 0; kk < BK; kk++) {
            float ra[4], rb[4];
#pragma unroll
            for (int i = 0; i < 4; i++) ra[i] = As[kk][tr*4 + i];
#pragma unroll
            for (int j = 0; j < 4; j++) rb[j] = Bs[kk][tc*4 + j];
#pragma unroll
            for (int i = 0; i < 4; i++)
#pragma unroll
                for (int j = 0; j < 4; j++)
                    acc[i][j] = fmaf(ra[i], rb[j], acc[i][j]);
        }
        __syncthreads();
    }

    float* Cb = Out + (size_t)b * Cq * Pq;
    float lsum = 0.f, lsq = 0.f;
#pragma unroll
    for (int i = 0; i < 4; i++) {
        int o = om + tr*4 + i;
        float4 v = make_float4(acc[i][0], acc[i][1], acc[i][2], acc[i][3]);
        *(float4*)(Cb + (size_t)o * Pq + pn + tc*4) = v;
        if (STATS) {
            lsum += v.x + v.y + v.z + v.w;
            lsq  += v.x*v.x + v.y*v.y + v.z*v.z + v.w*v.w;
        }
    }
    if (STATS) {
        __shared__ float ssum[2], ssq[2];
        if (tid < 2) { ssum[tid] = 0.f; ssq[tid] = 0.f; }
        __syncthreads();
        int grp = (tr * 4) >> 5;           // 0 or 1: which 32-row group in this tile
        atomicAdd(&ssum[grp], lsum);
        atomicAdd(&ssq[grp],  lsq);
        __syncthreads();
        if (tid < 2) {
            int g = b * NHq + (om + tid * 32) / HDq;
            atomicAdd(&g_sum[g], ssum[tid]);
            atomicAdd(&g_sq[g],  ssq[tid]);
        }
    }
}

// Bilinear sampling from g_V into g_S (both (B,C,P)); per-(b,head) slice is 2MB -> L2 resident
__global__ void k_sample() {
    int p  = blockIdx.x * blockDim.x + threadIdx.x;
    int hh = blockIdx.y;
    int b  = blockIdx.z;
    int bh = b * NHq + hh;

    float ix = g_ix[bh*Pq + p];
    float iy = g_iy[bh*Pq + p];
    float x0f = floorf(ix), y0f = floorf(iy);
    float wx = ix - x0f, wy = iy - y0f;
    int x0 = min(max((int)x0f,     0), Wq - 1);
    int x1 = min(max((int)x0f + 1, 0), Wq - 1);
    int y0 = min(max((int)y0f,     0), Hq - 1);
    int y1 = min(max((int)y0f + 1, 0), Hq - 1);
    float w00 = (1.f-wx)*(1.f-wy), w01 = wx*(1.f-wy);
    float w10 = (1.f-wx)*wy,       w11 = wx*wy;

    const float* Vb = g_V + ((size_t)b * Cq + hh * HDq) * Pq;
    float*       Sb = g_S + ((size_t)b * Cq + hh * HDq) * Pq;
    int i00 = y0*Wq + x0, i01 = y0*Wq + x1;
    int i10 = y1*Wq + x0, i11 = y1*Wq + x1;

#pragma unroll 8
    for (int d = 0; d < HDq; d++) {
        const float* Vd = Vb + d * Pq;
        float v = w00 * __ldg(Vd + i00) + w01 * __ldg(Vd + i01)
                + w10 * __ldg(Vd + i10) + w11 * __ldg(Vd + i11);
        Sb[d*Pq + p] = v;
    }
}

__global__ void k_finalize() {
    int g = threadIdx.x;
    if (g < NGq) {
        float n  = (float)(HDq * Pq);
        float mu = g_sum[g] / n;
        float var = g_sq[g] / n - mu * mu;
        g_mean[g] = mu;
        g_rstd[g] = rsqrtf(var + 1e-5f);
    }
}

// out = x + (pre - mean)*rstd*gamma + beta   (in-place on d_out)
__global__ void k_norm(const float* __restrict__ x,
                       const float* __restrict__ gamma,
                       const float* __restrict__ beta,
                       float* __restrict__ out) {
    size_t i = (size_t)blockIdx.x * blockDim.x + threadIdx.x;
    int c = (int)((i / Pq) % Cq);
    int b = (int)(i / ((size_t)Cq * Pq));
    int g = b * NHq + c / HDq;
    float v = out[i];
    out[i] = x[i] + (v - g_mean[g]) * g_rstd[g] * __ldg(gamma + c) + __ldg(beta + c);
}

extern "C" void kernel_launch(void* const* d_in, const int* in_sizes, int n_in,
                              void* d_out, int out_size) {
    const float* x     = (const float*)d_in[0];
    const float* dw    = (const float*)d_in[1];
    const float* offw  = (const float*)d_in[2];
    const float* offb  = (const float*)d_in[3];
    const float* vw    = (const float*)d_in[4];
    const float* ow    = (const float*)d_in[5];
    const float* gamma = (const float*)d_in[6];
    const float* beta  = (const float*)d_in[7];
    float* out = (float*)d_out;

    k_zero<<<1, 64>>>();
    k_offsets<<<dim3(Pq/256, Bq), 256>>>(x, dw, offw, offb);

    float* gV = nullptr; cudaGetSymbolAddress((void**)&gV, g_V);
    float* gS = nullptr; cudaGetSymbolAddress((void**)&gS, g_S);

    // V projection: g_V = vw @ x
    k_gemm<false><<<dim3(Pq/64, Cq/64, Bq), 256>>>(vw, x, gV);
    // Bilinear sampling
    k_sample<<<dim3(Pq/256, NHq, Bq), 256>>>();
    // O projection + groupnorm stats, pre-norm result straight into d_out
    k_gemm<true><<<dim3(Pq/64, Cq/64, Bq), 256>>>(ow, gS, out);
    k_finalize<<<1, 64>>>();
    k_norm<<<(Bq*Cq*Pq)/256, 256>>>(x, gamma, beta, out);
}

// round 3
// speedup vs baseline: 1.6736x; 1.6736x over previous
#include <cuda_runtime.h>
#include <cuda_bf16.h>
#include <math.h>
#include <stdint.h>

#define Bq 8
#define Cq 256
#define Hq 128
#define Wq 128
#define Pq (Hq*Wq)
#define NHq 8
#define HDq 32
#define NGq (Bq*NHq)

// Scratch (no allocations allowed)
__device__ float g_ix[Bq*NHq*Pq];
__device__ float g_iy[Bq*NHq*Pq];
__device__ float g_V [Bq*Cq*Pq];   // V projection, (B,C,P)
__device__ float g_S [Bq*Cq*Pq];   // bilinear-sampled, (B,C,P)
__device__ float g_sum[NGq];
__device__ float g_sq [NGq];
__device__ float g_mean[NGq];
__device__ float g_rstd[NGq];

// ---------------------------------------------------------------- helpers
__device__ __forceinline__ uint32_t smem_u32(const void* p) {
    uint32_t a;
    asm("{ .reg .u64 t; cvta.to.shared.u64 t, %1; cvt.u32.u64 %0, t; }" : "=r"(a) : "l"(p));
    return a;
}

__device__ __forceinline__ uint32_t swz(uint32_t byte) {
    return byte ^ ((byte >> 3) & 0x70);
}

__device__ __forceinline__ void ldsm4(uint32_t* r, uint32_t a) {
    asm volatile("ldmatrix.sync.aligned.m8n8.x4.shared.b16 {%0,%1,%2,%3}, [%4];"
        : "=r"(r[0]), "=r"(r[1]), "=r"(r[2]), "=r"(r[3]) : "r"(a));
}

__device__ __forceinline__ void mma16816(float* d, const uint32_t* a, const uint32_t* b) {
    asm volatile(
        "mma.sync.aligned.m16n8k16.row.col.f32.bf16.bf16.f32 "
        "{%0,%1,%2,%3}, {%4,%5,%6,%7}, {%8,%9}, {%0,%1,%2,%3};"
        : "+f"(d[0]), "+f"(d[1]), "+f"(d[2]), "+f"(d[3])
        : "r"(a[0]), "r"(a[1]), "r"(a[2]), "r"(a[3]), "r"(b[0]), "r"(b[1]));
}

// A-fragment ldmatrix address: A tile row-major [128 m][64 k] bf16 (128B rows), swizzled
__device__ __forceinline__ uint32_t a_addr(uint32_t base, int m_base, int kb, int lane) {
    int mat = lane >> 3, r = lane & 7;
    int row = m_base + ((mat & 1) << 3) + r;
    int col = kb + ((mat >> 1) << 3);
    return base + swz((uint32_t)(row * 128 + col * 2));
}

// B-fragment ldmatrix address: Bt tile row-major [128 n][64 k] bf16
__device__ __forceinline__ uint32_t b_addr(uint32_t base, int n_base, int kb, int lane) {
    int mat = lane >> 3, r = lane & 7;
    int row = n_base + ((mat >> 1) << 3) + r;
    int col = kb + ((mat & 1) << 3);
    return base + swz((uint32_t)(row * 128 + col * 2));
}

// ---------------------------------------------------------------- small kernels
__global__ void k_zero() {
    int i = threadIdx.x;
    if (i < NGq) { g_sum[i] = 0.f; g_sq[i] = 0.f; }
}

__global__ void k_offsets(const float* __restrict__ x,
                          const float* __restrict__ dw,
                          const float* __restrict__ offw,
                          const float* __restrict__ offb) {
    int p = blockIdx.x * blockDim.x + threadIdx.x;
    int b = blockIdx.y;
    int y = p / Wq, xx = p % Wq;

    float acc[2*NHq];
#pragma unroll
    for (int o = 0; o < 2*NHq; o++) acc[o] = __ldg(offb + o);

    const float* xb = x + (size_t)b * Cq * Pq;
    for (int c = 0; c < Cq; c++) {
        const float* xc = xb + c * Pq;
        float wreg[9];
#pragma unroll
        for (int t = 0; t < 9; t++) wreg[t] = __ldg(dw + c*9 + t);
        float hv = 0.f;
#pragma unroll
        for (int ky = 0; ky < 3; ky++) {
            int yy = y + ky - 1;
            if (yy < 0 || yy >= Hq) continue;
#pragma unroll
            for (int kx = 0; kx < 3; kx++) {
                int xk = xx + kx - 1;
                if (xk < 0 || xk >= Wq) continue;
                hv = fmaf(__ldg(xc + yy*Wq + xk), wreg[ky*3+kx], hv);
            }
        }
#pragma unroll
        for (int o = 0; o < 2*NHq; o++)
            acc[o] = fmaf(hv, __ldg(offw + o*Cq + c), acc[o]);
    }

    float gy = -1.f + 2.f * (float)y  / (float)(Hq - 1);
    float gx = -1.f + 2.f * (float)xx / (float)(Wq - 1);
#pragma unroll
    for (int hh = 0; hh < NHq; hh++) {
        float dy = tanhf(acc[2*hh  ]) * 0.5f;
        float dx = tanhf(acc[2*hh+1]) * 0.5f;
        float sy = fminf(fmaxf(gy + dy, -1.f), 1.f);
        float sx = fminf(fmaxf(gx + dx, -1.f), 1.f);
        g_iy[(b*NHq + hh)*Pq + p] = (sy + 1.f) * 0.5f * (float)(Hq - 1);
        g_ix[(b*NHq + hh)*Pq + p] = (sx + 1.f) * 0.5f * (float)(Wq - 1);
    }
}

__global__ void k_sample() {
    int p  = blockIdx.x * blockDim.x + threadIdx.x;
    int hh = blockIdx.y;
    int b  = blockIdx.z;
    int bh = b * NHq + hh;

    float ix = g_ix[bh*Pq + p];
    float iy = g_iy[bh*Pq + p];
    float x0f = floorf(ix), y0f = floorf(iy);
    float wx = ix - x0f, wy = iy - y0f;
    int x0 = min(max((int)x0f,     0), Wq - 1);
    int x1 = min(max((int)x0f + 1, 0), Wq - 1);
    int y0 = min(max((int)y0f,     0), Hq - 1);
    int y1 = min(max((int)y0f + 1, 0), Hq - 1);
    float w00 = (1.f-wx)*(1.f-wy), w01 = wx*(1.f-wy);
    float w10 = (1.f-wx)*wy,       w11 = wx*wy;

    const float* Vb = g_V + ((size_t)b * Cq + hh * HDq) * Pq;
    float*       Sb = g_S + ((size_t)b * Cq + hh * HDq) * Pq;
    int i00 = y0*Wq + x0, i01 = y0*Wq + x1;
    int i10 = y1*Wq + x0, i11 = y1*Wq + x1;

#pragma unroll 8
    for (int d = 0; d < HDq; d++) {
        const float* Vd = Vb + d * Pq;
        float v = w00 * __ldg(Vd + i00) + w01 * __ldg(Vd + i01)
                + w10 * __ldg(Vd + i10) + w11 * __ldg(Vd + i11);
        Sb[d*Pq + p] = v;
    }
}

__global__ void k_finalize() {
    int g = threadIdx.x;
    if (g < NGq) {
        float n  = (float)(HDq * Pq);
        float mu = g_sum[g] / n;
        float var = g_sq[g] / n - mu * mu;
        g_mean[g] = mu;
        g_rstd[g] = rsqrtf(var + 1e-5f);
    }
}

__global__ void k_norm(const float* __restrict__ x,
                       const float* __restrict__ gamma,
                       const float* __restrict__ beta,
                       float* __restrict__ out) {
    size_t i = (size_t)blockIdx.x * blockDim.x + threadIdx.x;
    int c = (int)((i / Pq) % Cq);
    int b = (int)(i / ((size_t)Cq * Pq));
    int g = b * NHq + c / HDq;
    float v = out[i];
    out[i] = x[i] + (v - g_mean[g]) * g_rstd[g] * __ldg(gamma + c) + __ldg(beta + c);
}

// ---------------------------------------------------------------- HMMA GEMM
// Out[b][o][p] = sum_c W[o][c] * In[b][c][p], fp32 via bf16 hi/lo split (3 passes).
// Block tile M=128(o) x N=128(p), K-chunks 64. Warp grid 2(M)x4(N), warp tile 64x32.
// SMEM: A hi/lo [128m][64k], Bt hi/lo [128n][64k] — all 128B rows, XOR-swizzled.
#define SMEM_GEMM_BYTES (65536 + 64)

template<bool STATS>
__global__ void __launch_bounds__(256, 2) k_gemm_mma(const float* __restrict__ W,
                                                     const float* __restrict__ In,
                                                     float* __restrict__ Out) {
    extern __shared__ char dsm[];
    const int tid   = threadIdx.x;
    const int lane  = tid & 31;
    const int wid   = tid >> 5;
    const int b     = blockIdx.z;
    const int om    = blockIdx.y * 128;
    const int p0    = blockIdx.x * 128;
    const int mwarp = wid & 1;       // 0-1 -> m offset 64*mwarp
    const int nwarp = wid >> 1;      // 0-3 -> n offset 32*nwarp

    uint32_t sb = smem_u32(dsm);
    const uint32_t sA_hi = sb;               // +16384 = lo
    const uint32_t sB_hi = sb + 32768;       // +16384 = lo
    char* pA_hi = dsm;
    char* pA_lo = dsm + 16384;
    char* pB_hi = dsm + 32768;
    char* pB_lo = dsm + 49152;
    float* ssum = (float*)(dsm + 65536);     // 8 floats: sum[4], sq[4]
    if (STATS && tid < 8) ssum[tid] = 0.f;

    float acc[4][4][4] = {};
    const float* Inb = In + (size_t)b * Cq * Pq;

    for (int kc = 0; kc < 4; kc++) {
        const int k0 = kc * 64;
        __syncthreads();

        // --- A tile: 128 rows(m) x 64 cols(k), float4 along k ---
#pragma unroll
        for (int i = 0; i < 8; i++) {
            int idx4 = tid + i * 256;
            int row  = idx4 >> 4;
            int c4   = (idx4 & 15) * 4;
            float4 v = *(const float4*)(W + (size_t)(om + row) * Cq + k0 + c4);
            __nv_bfloat16 h0 = __float2bfloat16(v.x);
            __nv_bfloat16 h1 = __float2bfloat16(v.y);
            __nv_bfloat16 h2 = __float2bfloat16(v.z);
            __nv_bfloat16 h3 = __float2bfloat16(v.w);
            __nv_bfloat16 l0 = __float2bfloat16(v.x - __bfloat162float(h0));
            __nv_bfloat16 l1 = __float2bfloat16(v.y - __bfloat162float(h1));
            __nv_bfloat16 l2 = __float2bfloat16(v.z - __bfloat162float(h2));
            __nv_bfloat16 l3 = __float2bfloat16(v.w - __bfloat162float(h3));
            uint32_t sw = swz((uint32_t)(row * 128 + c4 * 2));
            uint32_t h01 = (uint32_t)__bfloat16_as_ushort(h0) | ((uint32_t)__bfloat16_as_ushort(h1) << 16);
            uint32_t h23 = (uint32_t)__bfloat16_as_ushort(h2) | ((uint32_t)__bfloat16_as_ushort(h3) << 16);
            uint32_t l01 = (uint32_t)__bfloat16_as_ushort(l0) | ((uint32_t)__bfloat16_as_ushort(l1) << 16);
            uint32_t l23 = (uint32_t)__bfloat16_as_ushort(l2) | ((uint32_t)__bfloat16_as_ushort(l3) << 16);
            *(uint32_t*)(pA_hi + sw)     = h01;
            *(uint32_t*)(pA_hi + sw + 4) = h23;
            *(uint32_t*)(pA_lo + sw)     = l01;
            *(uint32_t*)(pA_lo + sw + 4) = l23;
        }

        // --- B tile: 128 rows(n=p) x 64 cols(k=c), transposed from (c,p) global ---
#pragma unroll
        for (int i = 0; i < 32; i++) {
            int idx = tid + i * 256;
            int n = idx & 127;               // coalesced across lanes
            int k = idx >> 7;
            float v = __ldg(Inb + (size_t)(k0 + k) * Pq + p0 + n);
            __nv_bfloat16 h = __float2bfloat16(v);
            __nv_bfloat16 l = __float2bfloat16(v - __bfloat162float(h));
            uint32_t sw = swz((uint32_t)(n * 128 + k * 2));
            *(__nv_bfloat16*)(pB_hi + sw) = h;
            *(__nv_bfloat16*)(pB_lo + sw) = l;
        }
        __syncthreads();

        // --- MMA over 4 k16 steps ---
#pragma unroll
        for (int ks = 0; ks < 4; ks++) {
            const int kb = ks * 16;
            uint32_t bh[8], bl[8];
#pragma unroll
            for (int t2 = 0; t2 < 2; t2++) {
                uint32_t ab = b_addr(sB_hi, nwarp * 32 + t2 * 16, kb, lane);
                ldsm4(&bh[t2 * 4], ab);
                ldsm4(&bl[t2 * 4], ab + 16384);
            }
#pragma unroll
            for (int mt = 0; mt < 4; mt++) {
                uint32_t aa = a_addr(sA_hi, mwarp * 64 + mt * 16, kb, lane);
                uint32_t ah[4], al[4];
                ldsm4(ah, aa);
                ldsm4(al, aa + 16384);
#pragma unroll
                for (int nt = 0; nt < 4; nt++) {
                    mma16816(acc[mt][nt], ah, &bh[nt * 2]);
                    mma16816(acc[mt][nt], ah, &bl[nt * 2]);
                    mma16816(acc[mt][nt], al, &bh[nt * 2]);
                }
            }
        }
    }

    // --- Epilogue: direct register -> global stores, optional groupnorm stats ---
    const int g  = lane >> 2;       // 0..7
    const int s2 = (lane & 3) * 2;  // 0,2,4,6
    float* Ob = Out + (size_t)b * Cq * Pq;
    float slocal[2] = {0.f, 0.f}, qlocal[2] = {0.f, 0.f};

#pragma unroll
    for (int mt = 0; mt < 4; mt++) {
        int o0 = om + mwarp * 64 + mt * 16 + g;
#pragma unroll
        for (int nt = 0; nt < 4; nt++) {
            int p = p0 + nwarp * 32 + nt * 8 + s2;
            float d0 = acc[mt][nt][0], d1 = acc[mt][nt][1];
            float d2 = acc[mt][nt][2], d3 = acc[mt][nt][3];
            *(float2*)(Ob + (size_t)o0 * Pq + p)       = make_float2(d0, d1);
            *(float2*)(Ob + (size_t)(o0 + 8) * Pq + p) = make_float2(d2, d3);
            if (STATS) {
                int j = mt >> 1;
                slocal[j] += d0 + d1 + d2 + d3;
                qlocal[j] += d0*d0 + d1*d1 + d2*d2 + d3*d3;
            }
        }
    }

    if (STATS) {
#pragma unroll
        for (int j = 0; j < 2; j++) {
#pragma unroll
            for (int o = 16; o; o >>= 1) {
                slocal[j] += __shfl_xor_sync(0xFFFFFFFFu, slocal[j], o);
                qlocal[j] += __shfl_xor_sync(0xFFFFFFFFu, qlocal[j], o);
            }
            if (lane == 0) {
                int gidx = mwarp * 2 + j;
                atomicAdd(&ssum[gidx],     slocal[j]);
                atomicAdd(&ssum[4 + gidx], qlocal[j]);
            }
        }
        __syncthreads();
        if (tid < 4) {
            int gg = b * NHq + blockIdx.y * 4 + tid;
            atomicAdd(&g_sum[gg], ssum[tid]);
            atomicAdd(&g_sq[gg],  ssum[4 + tid]);
        }
    }
}

// ---------------------------------------------------------------- launch
extern "C" void kernel_launch(void* const* d_in, const int* in_sizes, int n_in,
                              void* d_out, int out_size) {
    const float* x     = (const float*)d_in[0];
    const float* dw    = (const float*)d_in[1];
    const float* offw  = (const float*)d_in[2];
    const float* offb  = (const float*)d_in[3];
    const float* vw    = (const float*)d_in[4];
    const float* ow    = (const float*)d_in[5];
    const float* gamma = (const float*)d_in[6];
    const float* beta  = (const float*)d_in[7];
    float* out = (float*)d_out;

    cudaFuncSetAttribute(k_gemm_mma<false>, cudaFuncAttributeMaxDynamicSharedMemorySize, SMEM_GEMM_BYTES);
    cudaFuncSetAttribute(k_gemm_mma<true>,  cudaFuncAttributeMaxDynamicSharedMemorySize, SMEM_GEMM_BYTES);

    float* gV = nullptr; cudaGetSymbolAddress((void**)&gV, g_V);
    float* gS = nullptr; cudaGetSymbolAddress((void**)&gS, g_S);

    k_zero<<<1, 64>>>();
    k_offsets<<<dim3(Pq/256, Bq), 256>>>(x, dw, offw, offb);

    // V projection: g_V = vw @ x
    k_gemm_mma<false><<<dim3(Pq/128, Cq/128, Bq), 256, SMEM_GEMM_BYTES>>>(vw, x, gV);
    // Bilinear sampling
    k_sample<<<dim3(Pq/256, NHq, Bq), 256>>>();
    // O projection + groupnorm stats, straight into d_out
    k_gemm_mma<true><<<dim3(Pq/128, Cq/128, Bq), 256, SMEM_GEMM_BYTES>>>(ow, gS, out);
    k_finalize<<<1, 64>>>();
    k_norm<<<(Bq*Cq*Pq)/256, 256>>>(x, gamma, beta, out);
}